// round 2
// baseline (speedup 1.0000x reference)
#include <cuda_runtime.h>
#include <math.h>

#define NB 16
#define NT 512
#define NH 1024
#define NL 8192
#define ND 256

typedef unsigned long long u64;

// K,V stored transposed per batch: [b][d][t]
__device__ float g_K[NB * ND * NT];
__device__ float g_V[NB * ND * NT];

__device__ __forceinline__ void fma2(u64& d, u64 a, u64 b) {
    asm("fma.rn.f32x2 %0, %1, %2, %0;" : "+l"(d) : "l"(a), "l"(b));
}
__device__ __forceinline__ u64 pack2(float lo, float hi) {
    u64 r; asm("mov.b64 %0, {%1, %2};" : "=l"(r) : "f"(lo), "f"(hi)); return r;
}
__device__ __forceinline__ float2 unpack2(u64 v) {
    float2 r; asm("mov.b64 {%0, %1}, %2;" : "=f"(r.x), "=f"(r.y) : "l"(v)); return r;
}
// segment swizzle: disperses 16B segments across bank groups; row-xor disperses stores
__device__ __forceinline__ int swz(int seg, int row) {
    return seg ^ ((seg >> 3) & 7) ^ (row & 7);
}
__device__ __forceinline__ void ld8(float* r, const float* p) {
    float4 v0 = *(const float4*)p;
    float4 v1 = *(const float4*)(p + 4);
    r[0] = v0.x; r[1] = v0.y; r[2] = v0.z; r[3] = v0.w;
    r[4] = v1.x; r[5] = v1.y; r[6] = v1.z; r[7] = v1.w;
}

// ---------------------------------------------------------------------------
// Kernel 1: K/V projection with packed f32x2 FMA.
// Each CTA: 128 bt-rows x 128 n-cols, computing BOTH K (lo lane) and V (hi lane).
// Bs holds (wk, wv) interleaved pairs, k-major, swizzled. grid (64,2), block 256.
// ---------------------------------------------------------------------------
__global__ __launch_bounds__(256, 1) void kv_kernel(
    const float* __restrict__ X,
    const float* __restrict__ Wk,
    const float* __restrict__ Wv)
{
    __shared__ __align__(16) float As[16][132];
    __shared__ __align__(16) float Bs[16 * 256];

    const int m0  = blockIdx.x * 128;
    const int n0  = blockIdx.y * 128;
    const int tid = threadIdx.x;
    const int ty  = tid >> 4;
    const int tx  = tid & 15;

    u64 acc[8][8];
#pragma unroll
    for (int i = 0; i < 8; i++)
#pragma unroll
        for (int j = 0; j < 8; j++) acc[i][j] = 0ull;

    for (int h0 = 0; h0 < NH; h0 += 16) {
        __syncthreads();
        // X tile transpose: 128 m x 16 h
#pragma unroll
        for (int r = 0; r < 2; r++) {
            int v = tid + r * 256;           // 0..511
            int m = v >> 2;                  // 0..127
            int q = v & 3;                   // h quad
            float4 x = *(const float4*)&X[(m0 + m) * NH + h0 + q * 4];
            As[q * 4 + 0][m] = x.x; As[q * 4 + 1][m] = x.y;
            As[q * 4 + 2][m] = x.z; As[q * 4 + 3][m] = x.w;
        }
        // (Wk,Wv) interleaved transpose: 128 n x 16 h
#pragma unroll
        for (int r = 0; r < 2; r++) {
            int v  = tid + r * 256;
            int n  = v >> 2;
            int hq = v & 3;
            float4 a = *(const float4*)&Wk[(n0 + n) * NH + h0 + hq * 4];
            float4 c = *(const float4*)&Wv[(n0 + n) * NH + h0 + hq * 4];
            const float* av = (const float*)&a;
            const float* cv = (const float*)&c;
            int segN = n >> 1, sub = (n & 1) * 2;
#pragma unroll
            for (int q = 0; q < 4; q++) {
                int row = hq * 4 + q;
                *(float2*)&Bs[row * 256 + swz(segN, row) * 4 + sub] =
                    make_float2(av[q], cv[q]);
            }
        }
        __syncthreads();
#pragma unroll
        for (int kk = 0; kk < 16; kk++) {
            float a[8];
            ld8(a, &As[kk][ty * 8]);
            u64 ap[8], b8[8];
#pragma unroll
            for (int i = 0; i < 8; i++) ap[i] = pack2(a[i], a[i]);
#pragma unroll
            for (int q = 0; q < 4; q++) {
                ulonglong2 tb = *(const ulonglong2*)&Bs[kk * 256 + swz(4 * tx + q, kk) * 4];
                b8[2 * q] = tb.x; b8[2 * q + 1] = tb.y;
            }
#pragma unroll
            for (int i = 0; i < 8; i++)
#pragma unroll
                for (int j = 0; j < 8; j++)
                    fma2(acc[i][j], ap[i], b8[j]);
        }
    }

#pragma unroll
    for (int i = 0; i < 8; i++) {
        int m = m0 + ty * 8 + i;
        int b = m >> 9;
        int t = m & 511;
#pragma unroll
        for (int j = 0; j < 8; j++) {
            int n = n0 + tx * 8 + j;
            float2 kv = unpack2(acc[i][j]);
            g_K[(b * ND + n) * NT + t] = kv.x;
            g_V[(b * ND + n) * NT + t] = kv.y;
        }
    }
}

// ---------------------------------------------------------------------------
// Kernel 2: fused dual-GEMM flash attention, packed f32x2.
// smem tiles hold (q*scale, w) label-pairs and (k, v) t-pairs interleaved, so
// each fma.rn.f32x2 accumulates S (lo) and U (hi) with zero pack instrs.
// Double-buffered (64KB dynamic smem), one barrier per d-iter.
// grid (64,16), block 256.
// ---------------------------------------------------------------------------
__global__ __launch_bounds__(256, 1) void attn_kernel(
    const float* __restrict__ Q,
    const float* __restrict__ W,
    const float* __restrict__ bias,
    const int*   __restrict__ mask,
    float*       __restrict__ out)
{
    extern __shared__ __align__(16) float sm[];   // [2 bufs][QW 4096 | KV 4096] floats
    __shared__ int msk[128];

    const int l0  = blockIdx.x * 128;
    const int b   = blockIdx.y;
    const int tid = threadIdx.x;
    const int ty  = tid >> 4;
    const int tx  = tid & 15;
    const float scale = 0.0625f;   // folded into Q at tile-store time

    float m8[8], dn8[8], nm8[8];
#pragma unroll
    for (int i = 0; i < 8; i++) { m8[i] = -1e30f; dn8[i] = 0.f; nm8[i] = 0.f; }

    for (int t0 = 0; t0 < NT; t0 += 128) {
        __syncthreads();
        if (tid < 128) msk[tid] = mask[b * NT + t0 + tid];

        u64 acc[8][8];
#pragma unroll
        for (int i = 0; i < 8; i++)
#pragma unroll
            for (int j = 0; j < 8; j++) acc[i][j] = 0ull;

        // ---- tile store helpers (inlined via macro-like lambdas) ----
        auto store_qw = [&](float* qw, int d0) {
#pragma unroll
            for (int r = 0; r < 2; r++) {
                int v = tid + r * 256;
                int l = v >> 2;
                int dq = v & 3;
                float4 qx = *(const float4*)&Q[(l0 + l) * ND + d0 + dq * 4];
                float4 wx = *(const float4*)&W[(l0 + l) * ND + d0 + dq * 4];
                const float* qv = (const float*)&qx;
                const float* wv = (const float*)&wx;
                int segL = l >> 1, sub = (l & 1) * 2;
#pragma unroll
                for (int q = 0; q < 4; q++) {
                    int row = dq * 4 + q;
                    *(float2*)&qw[row * 256 + swz(segL, row) * 4 + sub] =
                        make_float2(qv[q] * scale, wv[q]);
                }
            }
        };
        auto store_kv = [&](float* kv, int d0) {
#pragma unroll
            for (int r = 0; r < 2; r++) {
                int v  = tid + r * 256;
                int kk = v >> 5;
                int tq = v & 31;
                float4 kx = *(const float4*)&g_K[(b * ND + d0 + kk) * NT + t0 + tq * 4];
                float4 vx = *(const float4*)&g_V[(b * ND + d0 + kk) * NT + t0 + tq * 4];
                *(float4*)&kv[kk * 256 + swz(tq * 2, kk) * 4] =
                    make_float4(kx.x, vx.x, kx.y, vx.y);
                *(float4*)&kv[kk * 256 + swz(tq * 2 + 1, kk) * 4] =
                    make_float4(kx.z, vx.z, kx.w, vx.w);
            }
        };

        store_qw(sm, 0);
        store_kv(sm + 4096, 0);
        __syncthreads();

        for (int it = 0; it < 16; it++) {
            float* cqw = sm + (it & 1) * 8192;
            float* ckv = cqw + 4096;
            if (it < 15) {
                float* nqw = sm + ((it + 1) & 1) * 8192;
                store_qw(nqw, (it + 1) * 16);
                store_kv(nqw + 4096, (it + 1) * 16);
            }
#pragma unroll
            for (int kk = 0; kk < 16; kk++) {
                u64 a8[8], b8[8];
#pragma unroll
                for (int q = 0; q < 4; q++) {
                    ulonglong2 ta = *(const ulonglong2*)&cqw[kk * 256 + swz(4 * ty + q, kk) * 4];
                    a8[2 * q] = ta.x; a8[2 * q + 1] = ta.y;
                    ulonglong2 tb = *(const ulonglong2*)&ckv[kk * 256 + swz(4 * tx + q, kk) * 4];
                    b8[2 * q] = tb.x; b8[2 * q + 1] = tb.y;
                }
#pragma unroll
                for (int i = 0; i < 8; i++)
#pragma unroll
                    for (int j = 0; j < 8; j++)
                        fma2(acc[i][j], a8[i], b8[j]);
            }
            __syncthreads();
        }

        // flash-softmax chunk update (S already scaled)
        int mv[8];
#pragma unroll
        for (int j = 0; j < 8; j++) mv[j] = msk[tx * 8 + j];
#pragma unroll
        for (int i = 0; i < 8; i++) {
            float s[8], u[8];
#pragma unroll
            for (int j = 0; j < 8; j++) {
                float2 su = unpack2(acc[i][j]);
                s[j] = su.x; u[j] = su.y;
            }
            float cm = m8[i];
#pragma unroll
            for (int j = 0; j < 8; j++)
                if (mv[j]) cm = fmaxf(cm, s[j]);
            if (cm > m8[i]) {
                float f = __expf(m8[i] - cm);
                dn8[i] *= f; nm8[i] *= f; m8[i] = cm;
            }
#pragma unroll
            for (int j = 0; j < 8; j++) {
                if (mv[j]) {
                    float p = __expf(s[j] - m8[i]);
                    dn8[i] += p;
                    nm8[i] += p * u[j];
                }
            }
        }
    }

    // merge 16 column partials per label (reuse dynamic smem)
    __syncthreads();
#pragma unroll
    for (int i = 0; i < 8; i++) {
        int l = ty * 8 + i;
        sm[l * 16 + tx]        = m8[i];
        sm[2048 + l * 16 + tx] = dn8[i];
        sm[4096 + l * 16 + tx] = nm8[i];
    }
    __syncthreads();
    if (tid < 128) {
        float mm = -1e30f;
#pragma unroll
        for (int c = 0; c < 16; c++) mm = fmaxf(mm, sm[tid * 16 + c]);
        float dn = 0.f, nm = 0.f;
#pragma unroll
        for (int c = 0; c < 16; c++) {
            float f = __expf(sm[tid * 16 + c] - mm);
            dn += sm[2048 + tid * 16 + c] * f;
            nm += sm[4096 + tid * 16 + c] * f;
        }
        out[b * NL + l0 + tid] = nm / dn + bias[l0 + tid];
    }
}

extern "C" void kernel_launch(void* const* d_in, const int* in_sizes, int n_in,
                              void* d_out, int out_size) {
    const float* X       = (const float*)d_in[0];
    const int*   mask    = (const int*)  d_in[1];
    const float* queries = (const float*)d_in[2];
    const float* Wk      = (const float*)d_in[3];
    const float* Wv      = (const float*)d_in[4];
    const float* outw    = (const float*)d_in[5];
    const float* bias    = (const float*)d_in[6];
    float* out = (float*)d_out;

    dim3 g1(64, 2);
    kv_kernel<<<g1, 256>>>(X, Wk, Wv);

    cudaFuncSetAttribute(attn_kernel, cudaFuncAttributeMaxDynamicSharedMemorySize, 65536);
    dim3 g2(64, 16);
    attn_kernel<<<g2, 256, 65536>>>(queries, outw, bias, mask, out);
}

// round 4
// speedup vs baseline: 1.6217x; 1.6217x over previous
#include <cuda_runtime.h>
#include <cuda_bf16.h>
#include <cstdint>
#include <math.h>

#define NB 16
#define NT 512
#define NH 1024
#define NL 8192
#define ND 256

typedef unsigned int u32;

// Operands pre-packed in mma.sync fragment order (bf16 hi/lo splits).
// A arrays (Q,W): [mt(512)][kt(16)][lane(32)][8 elems] -> uint4 per lane
// B arrays (K,V): [b(16)][nt(64)][kt(16)][lane(32)][4 elems] -> uint2 per lane
__device__ uint4 g_Qh[NL * ND / 8];
__device__ uint4 g_Ql[NL * ND / 8];
__device__ uint4 g_Wh[NL * ND / 8];
__device__ uint4 g_Wl[NL * ND / 8];
__device__ uint4 g_Kh[NB * NT * ND / 8];
__device__ uint4 g_Kl[NB * NT * ND / 8];
__device__ uint4 g_Vh[NB * NT * ND / 8];
__device__ uint4 g_Vl[NB * NT * ND / 8];

__device__ __forceinline__ void mma16816(float* c, const uint4& a, const uint2& b) {
    asm("mma.sync.aligned.m16n8k16.row.col.f32.bf16.bf16.f32 "
        "{%0,%1,%2,%3}, {%4,%5,%6,%7}, {%8,%9}, {%0,%1,%2,%3};"
        : "+f"(c[0]), "+f"(c[1]), "+f"(c[2]), "+f"(c[3])
        : "r"(a.x), "r"(a.y), "r"(a.z), "r"(a.w), "r"(b.x), "r"(b.y));
}

__device__ __forceinline__ u32 bf16pair(float x0, float x1) {
    __nv_bfloat162 h = __floats2bfloat162_rn(x0, x1);
    return *(u32*)&h;
}

__device__ __forceinline__ void ld8(float* r, const float* p) {
    float4 v0 = *(const float4*)p; float4 v1 = *(const float4*)(p + 4);
    r[0]=v0.x; r[1]=v0.y; r[2]=v0.z; r[3]=v0.w; r[4]=v1.x; r[5]=v1.y; r[6]=v1.z; r[7]=v1.w;
}

// ---------------------------------------------------------------------------
// Kernel 1: K/V projection (scalar fp32, proven). Epilogue splits to bf16
// hi/lo and scatters into B-fragment order.
// ---------------------------------------------------------------------------
__global__ __launch_bounds__(256, 1) void kv_kernel(
    const float* __restrict__ X,
    const float* __restrict__ Wk,
    const float* __restrict__ Wv)
{
    __shared__ __align__(16) float As[32][132];
    __shared__ __align__(16) float Bs[32][132];

    const int m0  = blockIdx.x * 128;
    const int n0  = blockIdx.y * 128;
    const int tid = threadIdx.x;
    const int ty  = tid >> 4;
    const int tx  = tid & 15;

    const float* Wbase = (n0 < 256) ? Wk : Wv;
    const int    nb    = n0 & 255;
    u32* dh = (u32*)((n0 < 256) ? g_Kh : g_Vh);
    u32* dl = (u32*)((n0 < 256) ? g_Kl : g_Vl);

    float acc[8][8];
#pragma unroll
    for (int i = 0; i < 8; i++)
#pragma unroll
        for (int j = 0; j < 8; j++) acc[i][j] = 0.f;

    for (int h0 = 0; h0 < NH; h0 += 32) {
        __syncthreads();
#pragma unroll
        for (int r = 0; r < 4; r++) {
            int v = tid + r * 256;
            int m = v >> 3;
            int q = v & 7;
            float4 x = *(const float4*)&X[(m0 + m) * NH + h0 + q * 4];
            As[q * 4 + 0][m] = x.x; As[q * 4 + 1][m] = x.y;
            As[q * 4 + 2][m] = x.z; As[q * 4 + 3][m] = x.w;
            float4 w = *(const float4*)&Wbase[(nb + m) * NH + h0 + q * 4];
            Bs[q * 4 + 0][m] = w.x; Bs[q * 4 + 1][m] = w.y;
            Bs[q * 4 + 2][m] = w.z; Bs[q * 4 + 3][m] = w.w;
        }
        __syncthreads();
#pragma unroll
        for (int kk = 0; kk < 32; kk++) {
            float a[8], b[8];
            ld8(a, &As[kk][ty * 8]);
            ld8(b, &Bs[kk][tx * 8]);
#pragma unroll
            for (int i = 0; i < 8; i++)
#pragma unroll
                for (int j = 0; j < 8; j++)
                    acc[i][j] = fmaf(a[i], b[j], acc[i][j]);
        }
    }

    // Scatter into B-fragment layout: elem addr for (b,t,d):
    // nt=t>>3, r=t&7, kt=d>>4, kd=d&15, lane=r*4+((kd>>1)&3),
    // u32 index = (((b*64+nt)*16+kt)*32+lane)*2 + (kd>>3); low half = even d.
#pragma unroll
    for (int i = 0; i < 8; i++) {
        int m = m0 + ty * 8 + i;
        int bb = m >> 9, t = m & 511;
        int nt = t >> 3, r = t & 7;
        size_t rowb = ((size_t)bb * 64 + nt) * 16;
#pragma unroll
        for (int jp = 0; jp < 4; jp++) {
            int d  = nb + tx * 8 + jp * 2;
            int kt = d >> 4, kd = d & 15;
            int lane = r * 4 + ((kd >> 1) & 3);
            size_t idx = ((rowb + kt) * 32 + lane) * 2 + (kd >> 3);
            float x0 = acc[i][jp * 2], x1 = acc[i][jp * 2 + 1];
            __nv_bfloat16 h0 = __float2bfloat16(x0);
            __nv_bfloat16 h1 = __float2bfloat16(x1);
            float l0f = x0 - __bfloat162float(h0);
            float l1f = x1 - __bfloat162float(h1);
            dh[idx] = (u32)__bfloat16_as_ushort(h0) | ((u32)__bfloat16_as_ushort(h1) << 16);
            dl[idx] = bf16pair(l0f, l1f);
        }
    }
}

// ---------------------------------------------------------------------------
// Kernel 1b: split queries (scale folded) and out_weight into bf16 hi/lo,
// written in A-fragment order.
// elem8 for (l,d): mt=l>>4, r=l&15, rh=r>>3, kt=d>>4, kd=d&15,
// lane=(r&7)*4+((kd>>1)&3), elem8=(kd>>3)*4+rh*2+(kd&1)
// ---------------------------------------------------------------------------
__global__ void split_qw(const float* __restrict__ Q, const float* __restrict__ W) {
    int i = blockIdx.x * blockDim.x + threadIdx.x;   // one float4
    if (i >= NL * ND / 4) return;
    int l  = i >> 6;
    int d0 = (i & 63) * 4;
    float4 q = ((const float4*)Q)[i];
    float4 w = ((const float4*)W)[i];
    const float sc = 0.0625f;
    float qa[4] = {q.x * sc, q.y * sc, q.z * sc, q.w * sc};
    float wa[4] = {w.x, w.y, w.z, w.w};

    int mt = l >> 4, r = l & 15, rh = r >> 3;
    int lane_lo = (r & 7) * 4;
    u32* qh = (u32*)g_Qh; u32* ql = (u32*)g_Ql;
    u32* wh = (u32*)g_Wh; u32* wl = (u32*)g_Wl;
#pragma unroll
    for (int p = 0; p < 2; p++) {
        int d  = d0 + p * 2;
        int kt = d >> 4, kd = d & 15;
        int lane = lane_lo + ((kd >> 1) & 3);
        size_t idx = (((size_t)mt * 16 + kt) * 32 + lane) * 4 + (((kd >> 3) * 4 + rh * 2) >> 1);
        float x0 = qa[p * 2], x1 = qa[p * 2 + 1];
        float y0 = wa[p * 2], y1 = wa[p * 2 + 1];
        __nv_bfloat16 h0 = __float2bfloat16(x0), h1 = __float2bfloat16(x1);
        __nv_bfloat16 g0 = __float2bfloat16(y0), g1 = __float2bfloat16(y1);
        qh[idx] = (u32)__bfloat16_as_ushort(h0) | ((u32)__bfloat16_as_ushort(h1) << 16);
        ql[idx] = bf16pair(x0 - __bfloat162float(h0), x1 - __bfloat162float(h1));
        wh[idx] = (u32)__bfloat16_as_ushort(g0) | ((u32)__bfloat16_as_ushort(g1) << 16);
        wl[idx] = bf16pair(y0 - __bfloat162float(g0), y1 - __bfloat162float(g1));
    }
}

// ---------------------------------------------------------------------------
// Kernel 2: fused dual-GEMM flash attention via mma.sync bf16 (3-term split).
// 512 threads, CTA = (128 labels, batch). 4 T-chunks of 128.
// Warp w: wm=w>>1 (mtile), wt=w&1 (T half, 8 ntiles).
// ---------------------------------------------------------------------------
__global__ __launch_bounds__(512, 1) void attn_kernel(
    const float* __restrict__ bias,
    const int*   __restrict__ mask,
    float*       __restrict__ out)
{
    __shared__ int   smask[NT];
    __shared__ float sM[2][128], sD[2][128], sN[2][128];

    const int tid  = threadIdx.x;
    const int lane = tid & 31;
    const int w    = tid >> 5;
    const int wm   = w >> 1;
    const int wt   = w & 1;
    const int l0   = blockIdx.x * 128;
    const int b    = blockIdx.y;

    smask[tid] = mask[b * NT + tid];
    __syncthreads();

    const size_t aBase = ((size_t)blockIdx.x * 8 + wm) * 16;   // mt_g*16

    float mrun[2] = {-1e30f, -1e30f}, dnr[2] = {0.f, 0.f}, nmr[2] = {0.f, 0.f};

    for (int chunk = 0; chunk < 4; chunk++) {
        float sacc[32], uacc[32];
#pragma unroll
        for (int x = 0; x < 32; x++) { sacc[x] = 0.f; uacc[x] = 0.f; }

        const size_t bBase = ((size_t)b * 64 + chunk * 16 + wt * 8) * 16;
        const uint2* Bkh = (const uint2*)g_Kh;
        const uint2* Bkl = (const uint2*)g_Kl;
        const uint2* Bvh = (const uint2*)g_Vh;
        const uint2* Bvl = (const uint2*)g_Vl;

#pragma unroll 2
        for (int kt = 0; kt < 16; kt++) {
            size_t ai = (aBase + kt) * 32 + lane;
            uint4 qh = g_Qh[ai];
            uint4 ql = g_Ql[ai];
            uint4 wh = g_Wh[ai];
            uint4 wl = g_Wl[ai];
#pragma unroll
            for (int j = 0; j < 8; j++) {
                size_t bi = (bBase + (size_t)j * 16 + kt) * 32 + lane;
                uint2 kh = Bkh[bi], kl = Bkl[bi];
                uint2 vh = Bvh[bi], vl = Bvl[bi];
                mma16816(&sacc[j * 4], qh, kh);
                mma16816(&sacc[j * 4], qh, kl);
                mma16816(&sacc[j * 4], ql, kh);
                mma16816(&uacc[j * 4], wh, vh);
                mma16816(&uacc[j * 4], wh, vl);
                mma16816(&uacc[j * 4], wl, vh);
            }
        }

        // flash-softmax update: thread owns rows r and r+8 (h=0,1), 16 cols each
        const int cbase = chunk * 128 + wt * 64 + (lane & 3) * 2;
#pragma unroll
        for (int h = 0; h < 2; h++) {
            float mloc = -1e30f;
            int   mk[16];
            float sv[16];
#pragma unroll
            for (int j = 0; j < 8; j++)
#pragma unroll
                for (int e = 0; e < 2; e++) {
                    int idx = j * 2 + e;
                    mk[idx] = smask[cbase + j * 8 + e];
                    sv[idx] = sacc[j * 4 + h * 2 + e];
                    if (mk[idx]) mloc = fmaxf(mloc, sv[idx]);
                }
            mloc = fmaxf(mloc, __shfl_xor_sync(0xFFFFFFFFu, mloc, 1));
            mloc = fmaxf(mloc, __shfl_xor_sync(0xFFFFFFFFu, mloc, 2));
            float newm = fmaxf(mrun[h], mloc);
            float f = __expf(mrun[h] - newm);
            float ds = 0.f, ns = 0.f;
#pragma unroll
            for (int j = 0; j < 8; j++)
#pragma unroll
                for (int e = 0; e < 2; e++) {
                    int idx = j * 2 + e;
                    float p = mk[idx] ? __expf(sv[idx] - newm) : 0.f;
                    ds += p;
                    ns += p * uacc[j * 4 + h * 2 + e];
                }
            ds += __shfl_xor_sync(0xFFFFFFFFu, ds, 1);
            ds += __shfl_xor_sync(0xFFFFFFFFu, ds, 2);
            ns += __shfl_xor_sync(0xFFFFFFFFu, ns, 1);
            ns += __shfl_xor_sync(0xFFFFFFFFu, ns, 2);
            dnr[h] = dnr[h] * f + ds;
            nmr[h] = nmr[h] * f + ns;
            mrun[h] = newm;
        }
    }

    // merge the two T-half warps per row
    if ((lane & 3) == 0) {
#pragma unroll
        for (int h = 0; h < 2; h++) {
            int rl = wm * 16 + (lane >> 2) + h * 8;
            sM[wt][rl] = mrun[h];
            sD[wt][rl] = dnr[h];
            sN[wt][rl] = nmr[h];
        }
    }
    __syncthreads();
    if (tid < 128) {
        float m0 = sM[0][tid], m1 = sM[1][tid];
        float mm = fmaxf(m0, m1);
        float f0 = __expf(m0 - mm), f1 = __expf(m1 - mm);
        float dn = sD[0][tid] * f0 + sD[1][tid] * f1;
        float nm = sN[0][tid] * f0 + sN[1][tid] * f1;
        out[b * NL + l0 + tid] = nm / dn + bias[l0 + tid];
    }
}

extern "C" void kernel_launch(void* const* d_in, const int* in_sizes, int n_in,
                              void* d_out, int out_size) {
    const float* X       = (const float*)d_in[0];
    const int*   mask    = (const int*)  d_in[1];
    const float* queries = (const float*)d_in[2];
    const float* Wk      = (const float*)d_in[3];
    const float* Wv      = (const float*)d_in[4];
    const float* outw    = (const float*)d_in[5];
    const float* bias    = (const float*)d_in[6];
    float* out = (float*)d_out;

    dim3 g1(64, 4);
    kv_kernel<<<g1, 256>>>(X, Wk, Wv);

    split_qw<<<(NL * ND / 4 + 255) / 256, 256>>>(queries, outw);

    dim3 g2(64, 16);
    attn_kernel<<<g2, 512>>>(bias, mask, out);
}

// round 5
// speedup vs baseline: 2.3958x; 1.4773x over previous
#include <cuda_runtime.h>
#include <cuda_bf16.h>
#include <cstdint>
#include <math.h>

#define NB 16
#define NT 512
#define NH 1024
#define NL 8192
#define ND 256

typedef unsigned int u32;

// Operands pre-packed in mma.sync fragment order (bf16 hi/lo splits).
// A arrays (Q,W): [mt(512)][kt(16)][lane(32)][8 elems] -> uint4 per lane
// B arrays (K,V): [b(16)][nt(64)][kt(16)][lane(32)][4 elems] -> uint2 per lane
__device__ uint4 g_Qh[NL * ND / 8];
__device__ uint4 g_Ql[NL * ND / 8];
__device__ uint4 g_Wh[NL * ND / 8];
__device__ uint4 g_Wl[NL * ND / 8];
__device__ uint4 g_Kh[NB * NT * ND / 8];
__device__ uint4 g_Kl[NB * NT * ND / 8];
__device__ uint4 g_Vh[NB * NT * ND / 8];
__device__ uint4 g_Vl[NB * NT * ND / 8];

__device__ __forceinline__ void mma16816(float* c, const uint4& a, const uint2& b) {
    asm("mma.sync.aligned.m16n8k16.row.col.f32.bf16.bf16.f32 "
        "{%0,%1,%2,%3}, {%4,%5,%6,%7}, {%8,%9}, {%0,%1,%2,%3};"
        : "+f"(c[0]), "+f"(c[1]), "+f"(c[2]), "+f"(c[3])
        : "r"(a.x), "r"(a.y), "r"(a.z), "r"(a.w), "r"(b.x), "r"(b.y));
}

__device__ __forceinline__ u32 bf16pair(float x0, float x1) {
    __nv_bfloat162 h = __floats2bfloat162_rn(x0, x1);
    return *(u32*)&h;
}
__device__ __forceinline__ u32 smem_u32(const void* p) {
    u32 a; asm("{ .reg .u64 t; cvta.to.shared.u64 t, %1; cvt.u32.u64 %0, t; }" : "=r"(a) : "l"(p));
    return a;
}
__device__ __forceinline__ void cpasync16(u32 dst, const void* src) {
    asm volatile("cp.async.cg.shared.global [%0], [%1], 16;" :: "r"(dst), "l"(src));
}
#define CP_COMMIT() asm volatile("cp.async.commit_group;" ::: "memory")
#define CP_WAIT0()  asm volatile("cp.async.wait_group 0;" ::: "memory")

__device__ __forceinline__ void ld8(float* r, const float* p) {
    float4 v0 = *(const float4*)p; float4 v1 = *(const float4*)(p + 4);
    r[0]=v0.x; r[1]=v0.y; r[2]=v0.z; r[3]=v0.w; r[4]=v1.x; r[5]=v1.y; r[6]=v1.z; r[7]=v1.w;
}

// ---------------------------------------------------------------------------
// Kernel 1: K/V projection (scalar fp32, proven). Epilogue splits to bf16
// hi/lo and scatters into B-fragment order.  (unchanged from round 4)
// ---------------------------------------------------------------------------
__global__ __launch_bounds__(256, 1) void kv_kernel(
    const float* __restrict__ X,
    const float* __restrict__ Wk,
    const float* __restrict__ Wv)
{
    __shared__ __align__(16) float As[32][132];
    __shared__ __align__(16) float Bs[32][132];

    const int m0  = blockIdx.x * 128;
    const int n0  = blockIdx.y * 128;
    const int tid = threadIdx.x;
    const int ty  = tid >> 4;
    const int tx  = tid & 15;

    const float* Wbase = (n0 < 256) ? Wk : Wv;
    const int    nb    = n0 & 255;
    u32* dh = (u32*)((n0 < 256) ? g_Kh : g_Vh);
    u32* dl = (u32*)((n0 < 256) ? g_Kl : g_Vl);

    float acc[8][8];
#pragma unroll
    for (int i = 0; i < 8; i++)
#pragma unroll
        for (int j = 0; j < 8; j++) acc[i][j] = 0.f;

    for (int h0 = 0; h0 < NH; h0 += 32) {
        __syncthreads();
#pragma unroll
        for (int r = 0; r < 4; r++) {
            int v = tid + r * 256;
            int m = v >> 3;
            int q = v & 7;
            float4 x = *(const float4*)&X[(m0 + m) * NH + h0 + q * 4];
            As[q * 4 + 0][m] = x.x; As[q * 4 + 1][m] = x.y;
            As[q * 4 + 2][m] = x.z; As[q * 4 + 3][m] = x.w;
            float4 w = *(const float4*)&Wbase[(nb + m) * NH + h0 + q * 4];
            Bs[q * 4 + 0][m] = w.x; Bs[q * 4 + 1][m] = w.y;
            Bs[q * 4 + 2][m] = w.z; Bs[q * 4 + 3][m] = w.w;
        }
        __syncthreads();
#pragma unroll
        for (int kk = 0; kk < 32; kk++) {
            float a[8], b[8];
            ld8(a, &As[kk][ty * 8]);
            ld8(b, &Bs[kk][tx * 8]);
#pragma unroll
            for (int i = 0; i < 8; i++)
#pragma unroll
                for (int j = 0; j < 8; j++)
                    acc[i][j] = fmaf(a[i], b[j], acc[i][j]);
        }
    }

#pragma unroll
    for (int i = 0; i < 8; i++) {
        int m = m0 + ty * 8 + i;
        int bb = m >> 9, t = m & 511;
        int nt = t >> 3, r = t & 7;
        size_t rowb = ((size_t)bb * 64 + nt) * 16;
#pragma unroll
        for (int jp = 0; jp < 4; jp++) {
            int d  = nb + tx * 8 + jp * 2;
            int kt = d >> 4, kd = d & 15;
            int lane = r * 4 + ((kd >> 1) & 3);
            size_t idx = ((rowb + kt) * 32 + lane) * 2 + (kd >> 3);
            float x0 = acc[i][jp * 2], x1 = acc[i][jp * 2 + 1];
            __nv_bfloat16 h0 = __float2bfloat16(x0);
            __nv_bfloat16 h1 = __float2bfloat16(x1);
            float l0f = x0 - __bfloat162float(h0);
            float l1f = x1 - __bfloat162float(h1);
            dh[idx] = (u32)__bfloat16_as_ushort(h0) | ((u32)__bfloat16_as_ushort(h1) << 16);
            dl[idx] = bf16pair(l0f, l1f);
        }
    }
}

// ---------------------------------------------------------------------------
// Kernel 1b: split queries (scale folded) and out_weight into bf16 hi/lo,
// written in A-fragment order.  (unchanged from round 4)
// ---------------------------------------------------------------------------
__global__ void split_qw(const float* __restrict__ Q, const float* __restrict__ W) {
    int i = blockIdx.x * blockDim.x + threadIdx.x;
    if (i >= NL * ND / 4) return;
    int l  = i >> 6;
    int d0 = (i & 63) * 4;
    float4 q = ((const float4*)Q)[i];
    float4 w = ((const float4*)W)[i];
    const float sc = 0.0625f;
    float qa[4] = {q.x * sc, q.y * sc, q.z * sc, q.w * sc};
    float wa[4] = {w.x, w.y, w.z, w.w};

    int mt = l >> 4, r = l & 15, rh = r >> 3;
    int lane_lo = (r & 7) * 4;
    u32* qh = (u32*)g_Qh; u32* ql = (u32*)g_Ql;
    u32* wh = (u32*)g_Wh; u32* wl = (u32*)g_Wl;
#pragma unroll
    for (int p = 0; p < 2; p++) {
        int d  = d0 + p * 2;
        int kt = d >> 4, kd = d & 15;
        int lane = lane_lo + ((kd >> 1) & 3);
        size_t idx = (((size_t)mt * 16 + kt) * 32 + lane) * 4 + (((kd >> 3) * 4 + rh * 2) >> 1);
        float x0 = qa[p * 2], x1 = qa[p * 2 + 1];
        float y0 = wa[p * 2], y1 = wa[p * 2 + 1];
        __nv_bfloat16 h0 = __float2bfloat16(x0), h1 = __float2bfloat16(x1);
        __nv_bfloat16 g0 = __float2bfloat16(y0), g1 = __float2bfloat16(y1);
        qh[idx] = (u32)__bfloat16_as_ushort(h0) | ((u32)__bfloat16_as_ushort(h1) << 16);
        ql[idx] = bf16pair(x0 - __bfloat162float(h0), x1 - __bfloat162float(h1));
        wh[idx] = (u32)__bfloat16_as_ushort(g0) | ((u32)__bfloat16_as_ushort(g1) << 16);
        wl[idx] = bf16pair(y0 - __bfloat162float(g0), y1 - __bfloat162float(g1));
    }
}

// ---------------------------------------------------------------------------
// Kernel 2: fused dual-GEMM flash attention via mma.sync bf16 (3-term split),
// now with cp.async smem staging (double-buffered 2x32KB) to remove the
// 8x B / 2x A L2-refetch redundancy.
// Dynamic smem stage layout (per buf, 32KB):
//   A: arr(4) x [mt(8)][lane(32)] uint4   at  arr*4096
//   B: arr(4) x [nt(16)][lane(32)] uint2  at  16384 + arr*4096
// ---------------------------------------------------------------------------
__global__ __launch_bounds__(512, 1) void attn_kernel(
    const float* __restrict__ bias,
    const int*   __restrict__ mask,
    float*       __restrict__ out)
{
    extern __shared__ __align__(16) char dsm[];
    __shared__ int   smask[NT];
    __shared__ float sM[2][128], sD[2][128], sN[2][128];

    const int tid  = threadIdx.x;
    const int lane = tid & 31;
    const int w    = tid >> 5;
    const int wm   = w >> 1;
    const int wt   = w & 1;
    const int l0   = blockIdx.x * 128;
    const int b    = blockIdx.y;
    const u32 smb  = smem_u32(dsm);

    smask[tid] = mask[b * NT + tid];

    // per-thread producer assignment
    const int grp = tid >> 7;          // array id 0..3
    const int gi  = tid & 127;
    const uint4* Asrc = (grp == 0) ? g_Qh : (grp == 1) ? g_Ql : (grp == 2) ? g_Wh : g_Wl;
    const uint4* Bsrc = (grp == 0) ? g_Kh : (grp == 1) ? g_Kl : (grp == 2) ? g_Vh : g_Vl;
    // A elements: e in {gi, gi+128}: mt=e>>5, lane=e&31
    const int amt0 = gi >> 5,          aln0 = gi & 31;
    const int amt1 = (gi + 128) >> 5,  aln1 = gi & 31;
    // B elements (uint4 = lane-pair): e in {gi, gi+128}: nt=e>>4, lp=e&15
    const int bnt0 = gi >> 4,          blp0 = gi & 15;
    const int bnt1 = (gi + 128) >> 4,  blp1 = gi & 15;

    const size_t aRow = (size_t)blockIdx.x * 8;   // global mt base

    float mrun[2] = {-1e30f, -1e30f}, dnr[2] = {0.f, 0.f}, nmr[2] = {0.f, 0.f};

    for (int chunk = 0; chunk < 4; chunk++) {
        float sacc[32], uacc[32];
#pragma unroll
        for (int x = 0; x < 32; x++) { sacc[x] = 0.f; uacc[x] = 0.f; }

        const size_t bRow = (size_t)b * 64 + chunk * 16;   // global nt base

        // ---- producer: issue one stage's cp.asyncs ----
        auto loadStage = [&](int buf, int kt) {
            u32 base = smb + buf * 32768 + grp * 4096;
            cpasync16(base + (amt0 * 32 + aln0) * 16,
                      Asrc + ((aRow + amt0) * 16 + kt) * 32 + aln0);
            cpasync16(base + (amt1 * 32 + aln1) * 16,
                      Asrc + ((aRow + amt1) * 16 + kt) * 32 + aln1);
            u32 bbase = base + 16384;
            cpasync16(bbase + (bnt0 * 16 + blp0) * 16,
                      Bsrc + ((bRow + bnt0) * 16 + kt) * 16 + blp0);
            cpasync16(bbase + (bnt1 * 16 + blp1) * 16,
                      Bsrc + ((bRow + bnt1) * 16 + kt) * 16 + blp1);
            CP_COMMIT();
        };

        // prologue: kt=0 into buf 0
        loadStage(0, 0);
        CP_WAIT0();
        __syncthreads();

        for (int kt = 0; kt < 16; kt++) {
            const int buf = kt & 1;
            if (kt < 15) loadStage(buf ^ 1, kt + 1);

            const char* sb = dsm + buf * 32768;
            uint4 qh = *(const uint4*)(sb +          (wm * 32 + lane) * 16);
            uint4 ql = *(const uint4*)(sb + 4096  +  (wm * 32 + lane) * 16);
            uint4 wh = *(const uint4*)(sb + 8192  +  (wm * 32 + lane) * 16);
            uint4 wl = *(const uint4*)(sb + 12288 +  (wm * 32 + lane) * 16);
            const char* bb = sb + 16384;
#pragma unroll
            for (int j = 0; j < 8; j++) {
                int nt = wt * 8 + j;
                uint2 kh = *(const uint2*)(bb +          (nt * 32 + lane) * 8);
                uint2 kl = *(const uint2*)(bb + 4096  +  (nt * 32 + lane) * 8);
                uint2 vh = *(const uint2*)(bb + 8192  +  (nt * 32 + lane) * 8);
                uint2 vl = *(const uint2*)(bb + 12288 +  (nt * 32 + lane) * 8);
                mma16816(&sacc[j * 4], qh, kh);
                mma16816(&sacc[j * 4], qh, kl);
                mma16816(&sacc[j * 4], ql, kh);
                mma16816(&uacc[j * 4], wh, vh);
                mma16816(&uacc[j * 4], wh, vl);
                mma16816(&uacc[j * 4], wl, vh);
            }
            if (kt < 15) CP_WAIT0();
            __syncthreads();
        }

        // flash-softmax update: thread owns rows r and r+8 (h=0,1), 16 cols each
        const int cbase = chunk * 128 + wt * 64 + (lane & 3) * 2;
#pragma unroll
        for (int h = 0; h < 2; h++) {
            float mloc = -1e30f;
            int   mk[16];
            float sv[16];
#pragma unroll
            for (int j = 0; j < 8; j++)
#pragma unroll
                for (int e = 0; e < 2; e++) {
                    int idx = j * 2 + e;
                    mk[idx] = smask[cbase + j * 8 + e];
                    sv[idx] = sacc[j * 4 + h * 2 + e];
                    if (mk[idx]) mloc = fmaxf(mloc, sv[idx]);
                }
            mloc = fmaxf(mloc, __shfl_xor_sync(0xFFFFFFFFu, mloc, 1));
            mloc = fmaxf(mloc, __shfl_xor_sync(0xFFFFFFFFu, mloc, 2));
            float newm = fmaxf(mrun[h], mloc);
            float f = __expf(mrun[h] - newm);
            float ds = 0.f, ns = 0.f;
#pragma unroll
            for (int j = 0; j < 8; j++)
#pragma unroll
                for (int e = 0; e < 2; e++) {
                    int idx = j * 2 + e;
                    float p = mk[idx] ? __expf(sv[idx] - newm) : 0.f;
                    ds += p;
                    ns += p * uacc[j * 4 + h * 2 + e];
                }
            ds += __shfl_xor_sync(0xFFFFFFFFu, ds, 1);
            ds += __shfl_xor_sync(0xFFFFFFFFu, ds, 2);
            ns += __shfl_xor_sync(0xFFFFFFFFu, ns, 1);
            ns += __shfl_xor_sync(0xFFFFFFFFu, ns, 2);
            dnr[h] = dnr[h] * f + ds;
            nmr[h] = nmr[h] * f + ns;
            mrun[h] = newm;
        }
    }

    // merge the two T-half warps per row
    if ((lane & 3) == 0) {
#pragma unroll
        for (int h = 0; h < 2; h++) {
            int rl = wm * 16 + (lane >> 2) + h * 8;
            sM[wt][rl] = mrun[h];
            sD[wt][rl] = dnr[h];
            sN[wt][rl] = nmr[h];
        }
    }
    __syncthreads();
    if (tid < 128) {
        float m0 = sM[0][tid], m1 = sM[1][tid];
        float mm = fmaxf(m0, m1);
        float f0 = __expf(m0 - mm), f1 = __expf(m1 - mm);
        float dn = sD[0][tid] * f0 + sD[1][tid] * f1;
        float nm = sN[0][tid] * f0 + sN[1][tid] * f1;
        out[b * NL + l0 + tid] = nm / dn + bias[l0 + tid];
    }
}

extern "C" void kernel_launch(void* const* d_in, const int* in_sizes, int n_in,
                              void* d_out, int out_size) {
    const float* X       = (const float*)d_in[0];
    const int*   mask    = (const int*)  d_in[1];
    const float* queries = (const float*)d_in[2];
    const float* Wk      = (const float*)d_in[3];
    const float* Wv      = (const float*)d_in[4];
    const float* outw    = (const float*)d_in[5];
    const float* bias    = (const float*)d_in[6];
    float* out = (float*)d_out;

    dim3 g1(64, 4);
    kv_kernel<<<g1, 256>>>(X, Wk, Wv);

    split_qw<<<(NL * ND / 4 + 255) / 256, 256>>>(queries, outw);

    cudaFuncSetAttribute(attn_kernel, cudaFuncAttributeMaxDynamicSharedMemorySize, 65536);
    dim3 g2(64, 16);
    attn_kernel<<<g2, 512, 65536>>>(bias, mask, out);
}

// round 6
// speedup vs baseline: 2.8999x; 1.2104x over previous
#include <cuda_runtime.h>
#include <cuda_bf16.h>
#include <cstdint>
#include <math.h>

#define NB 16
#define NT 512
#define NH 1024
#define NL 8192
#define ND 256

typedef unsigned int u32;

// ---- attn operands, mma.sync fragment order (bf16 hi/lo splits) ----
// A arrays (Q,W): [mt(512)][kt(16)][lane(32)] uint4
// B arrays (K,V): [b(16)][nt(64)][kt(16)][lane(32)] uint2
__device__ uint4 g_Qh[NL * ND / 8];
__device__ uint4 g_Ql[NL * ND / 8];
__device__ uint4 g_Wh[NL * ND / 8];
__device__ uint4 g_Wl[NL * ND / 8];
__device__ uint4 g_Kh[NB * NT * ND / 8];
__device__ uint4 g_Kl[NB * NT * ND / 8];
__device__ uint4 g_Vh[NB * NT * ND / 8];
__device__ uint4 g_Vl[NB * NT * ND / 8];

// ---- kv-gemm operands ----
// X A-frag: [mt(512)][kt(64)][lane(32)] uint4
__device__ uint4 g_Xh[NB * NT * NH / 8];
__device__ uint4 g_Xl[NB * NT * NH / 8];
// W B-frag: [nt(32)][kt(64)][lane(32)] uint2
__device__ uint2 g_Wkh[ND * NH / 4];
__device__ uint2 g_Wkl[ND * NH / 4];
__device__ uint2 g_Wvh[ND * NH / 4];
__device__ uint2 g_Wvl[ND * NH / 4];

__device__ __forceinline__ void mma16816(float* c, const uint4& a, const uint2& b) {
    asm("mma.sync.aligned.m16n8k16.row.col.f32.bf16.bf16.f32 "
        "{%0,%1,%2,%3}, {%4,%5,%6,%7}, {%8,%9}, {%0,%1,%2,%3};"
        : "+f"(c[0]), "+f"(c[1]), "+f"(c[2]), "+f"(c[3])
        : "r"(a.x), "r"(a.y), "r"(a.z), "r"(a.w), "r"(b.x), "r"(b.y));
}
__device__ __forceinline__ u32 bf16pair(float x0, float x1) {
    __nv_bfloat162 h = __floats2bfloat162_rn(x0, x1);
    return *(u32*)&h;
}
__device__ __forceinline__ u32 smem_u32(const void* p) {
    u32 a; asm("{ .reg .u64 t; cvta.to.shared.u64 t, %1; cvt.u32.u64 %0, t; }" : "=r"(a) : "l"(p));
    return a;
}
__device__ __forceinline__ void cpasync16(u32 dst, const void* src) {
    asm volatile("cp.async.cg.shared.global [%0], [%1], 16;" :: "r"(dst), "l"(src));
}
#define CP_COMMIT() asm volatile("cp.async.commit_group;" ::: "memory")
#define CP_WAIT0()  asm volatile("cp.async.wait_group 0;" ::: "memory")

// hi/lo split store helper: writes (h0|h1) u32 and (l0|l1) u32
__device__ __forceinline__ void split_store(u32* dh, u32* dl, size_t idx, float x0, float x1) {
    __nv_bfloat16 h0 = __float2bfloat16(x0);
    __nv_bfloat16 h1 = __float2bfloat16(x1);
    dh[idx] = (u32)__bfloat16_as_ushort(h0) | ((u32)__bfloat16_as_ushort(h1) << 16);
    dl[idx] = bf16pair(x0 - __bfloat162float(h0), x1 - __bfloat162float(h1));
}

// ---------------------------------------------------------------------------
// split_x: X fp32 [8192,1024] -> Xh/Xl in A-frag order (64 kt)
// ---------------------------------------------------------------------------
__global__ void split_x(const float* __restrict__ X) {
    int i = blockIdx.x * blockDim.x + threadIdx.x;   // one float4
    if (i >= NB * NT * NH / 4) return;
    int row = i >> 8;              // bt
    int h0  = (i & 255) * 4;
    float4 x = ((const float4*)X)[i];
    float xa[4] = {x.x, x.y, x.z, x.w};
    int mt = row >> 4, r = row & 15, rh = r >> 3;
    int lane_lo = (r & 7) * 4;
    u32* xh = (u32*)g_Xh; u32* xl = (u32*)g_Xl;
#pragma unroll
    for (int p = 0; p < 2; p++) {
        int d  = h0 + p * 2;
        int kt = d >> 4, kd = d & 15;
        int lane = lane_lo + ((kd >> 1) & 3);
        size_t idx = (((size_t)mt * 64 + kt) * 32 + lane) * 4 + ((kd >> 3) * 2 + rh);
        split_store(xh, xl, idx, xa[p * 2], xa[p * 2 + 1]);
    }
}

// ---------------------------------------------------------------------------
// split_w: Wk/Wv fp32 [256,1024] -> B-frag order (32 nt, 64 kt)
// ---------------------------------------------------------------------------
__global__ void split_w(const float* __restrict__ Wk, const float* __restrict__ Wv) {
    int i = blockIdx.x * blockDim.x + threadIdx.x;   // one float4
    if (i >= ND * NH / 4) return;
    const float* src = blockIdx.y ? Wv : Wk;
    u32* dh = (u32*)(blockIdx.y ? g_Wvh : g_Wkh);
    u32* dl = (u32*)(blockIdx.y ? g_Wvl : g_Wkl);
    int d  = i >> 8;               // output feature 0..255
    int h0 = (i & 255) * 4;
    float4 x = ((const float4*)src)[i];
    float xa[4] = {x.x, x.y, x.z, x.w};
    int nt = d >> 3, nr = d & 7;
#pragma unroll
    for (int p = 0; p < 2; p++) {
        int h  = h0 + p * 2;
        int kt = h >> 4, kd = h & 15;
        int lane = nr * 4 + ((kd >> 1) & 3);
        size_t idx = (((size_t)nt * 64 + kt) * 32 + lane) * 2 + (kd >> 3);
        split_store(dh, dl, idx, xa[p * 2], xa[p * 2 + 1]);
    }
}

// ---------------------------------------------------------------------------
// kv_mma: K/V projection via mma.sync bf16 3-term split.
// grid (64, 4): x = 128-row bt tile, y = ng (0,1 -> K halves; 2,3 -> V halves).
// 512 threads. cp.async double-buffered, 2 kt per stage (64KB dyn smem).
// Epilogue scatters h/l splits into attn B-frag layout.
// ---------------------------------------------------------------------------
__global__ __launch_bounds__(512, 1) void kv_mma(int dummy) {
    extern __shared__ __align__(16) char dsm[];
    const int tid  = threadIdx.x;
    const int lane = tid & 31;
    const int w    = tid >> 5;
    const int wm   = w >> 1;
    const int wt   = w & 1;
    const int ng   = blockIdx.y;
    const int isV  = ng >> 1;
    const int nhalf = ng & 1;
    const u32 smb  = smem_u32(dsm);

    const uint2* Bh = isV ? g_Wvh : g_Wkh;
    const uint2* Bl = isV ? g_Wvl : g_Wkl;
    u32* dh = (u32*)(isV ? g_Vh : g_Kh);
    u32* dl = (u32*)(isV ? g_Vl : g_Kl);

    const size_t aRow = (size_t)blockIdx.x * 8;        // mt base
    const size_t ntBase = (size_t)nhalf * 16;          // B nt base

    // producer assignment: grp 0=xh 1=xl 2=wh 3=wl; 2 chunks per kt each
    const int grp = tid >> 7;
    const int gi  = tid & 127;

    float acc[32];
#pragma unroll
    for (int x = 0; x < 32; x++) acc[x] = 0.f;

    auto loadStage = [&](int buf, int kt0) {
#pragma unroll
        for (int s = 0; s < 2; s++) {
            int kt = kt0 + s;
            u32 base = smb + buf * 32768 + s * 16384;
            if (grp < 2) {
                const uint4* src = grp ? g_Xl : g_Xh;
                u32 abase = base + grp * 4096;
#pragma unroll
                for (int e = 0; e < 2; e++) {
                    int el = gi + e * 128;
                    int mt = el >> 5, ln = el & 31;
                    cpasync16(abase + el * 16, src + ((aRow + mt) * 64 + kt) * 32 + ln);
                }
            } else {
                const uint4* src = (const uint4*)((grp == 2) ? Bh : Bl);
                u32 bbase = base + 8192 + (grp - 2) * 4096;
#pragma unroll
                for (int e = 0; e < 2; e++) {
                    int el = gi + e * 128;
                    int nt = el >> 4, lp = el & 15;
                    cpasync16(bbase + el * 16, src + ((ntBase + nt) * 64 + kt) * 16 + lp);
                }
            }
        }
        CP_COMMIT();
    };

    loadStage(0, 0);
    CP_WAIT0();
    __syncthreads();

    for (int st = 0; st < 32; st++) {
        const int buf = st & 1;
        if (st < 31) loadStage(buf ^ 1, (st + 1) * 2);
#pragma unroll
        for (int s = 0; s < 2; s++) {
            const char* sb = dsm + buf * 32768 + s * 16384;
            uint4 xh = *(const uint4*)(sb +        (wm * 32 + lane) * 16);
            uint4 xl = *(const uint4*)(sb + 4096 + (wm * 32 + lane) * 16);
            const char* bb = sb + 8192;
#pragma unroll
            for (int j = 0; j < 8; j++) {
                int nt = wt * 8 + j;
                uint2 wh = *(const uint2*)(bb +        (nt * 32 + lane) * 8);
                uint2 wl = *(const uint2*)(bb + 4096 + (nt * 32 + lane) * 8);
                mma16816(&acc[j * 4], xh, wh);
                mma16816(&acc[j * 4], xh, wl);
                mma16816(&acc[j * 4], xl, wh);
            }
        }
        if (st < 31) CP_WAIT0();
        __syncthreads();
    }

    // epilogue: scatter into attn B-frag layout
#pragma unroll
    for (int j = 0; j < 8; j++) {
        int d  = nhalf * 128 + wt * 64 + j * 8 + (lane & 3) * 2;
        int kt = d >> 4, kd = d & 15;
        int lane_lo = (kd >> 1) & 3;
#pragma unroll
        for (int h = 0; h < 2; h++) {
            int bt = blockIdx.x * 128 + wm * 16 + (lane >> 2) + h * 8;
            int bb2 = bt >> 9, t = bt & 511;
            int nt = t >> 3, rt = t & 7;
            size_t idx = ((((size_t)bb2 * 64 + nt) * 16 + kt) * 32 + rt * 4 + lane_lo) * 2 + (kd >> 3);
            split_store(dh, dl, idx, acc[j * 4 + h * 2], acc[j * 4 + h * 2 + 1]);
        }
    }
}

// ---------------------------------------------------------------------------
// split_qw: queries (scale folded) / out_weight -> A-frag hi/lo (unchanged)
// ---------------------------------------------------------------------------
__global__ void split_qw(const float* __restrict__ Q, const float* __restrict__ W) {
    int i = blockIdx.x * blockDim.x + threadIdx.x;
    if (i >= NL * ND / 4) return;
    int l  = i >> 6;
    int d0 = (i & 63) * 4;
    float4 q = ((const float4*)Q)[i];
    float4 w = ((const float4*)W)[i];
    const float sc = 0.0625f;
    float qa[4] = {q.x * sc, q.y * sc, q.z * sc, q.w * sc};
    float wa[4] = {w.x, w.y, w.z, w.w};

    int mt = l >> 4, r = l & 15, rh = r >> 3;
    int lane_lo = (r & 7) * 4;
    u32* qh = (u32*)g_Qh; u32* ql = (u32*)g_Ql;
    u32* wh = (u32*)g_Wh; u32* wl = (u32*)g_Wl;
#pragma unroll
    for (int p = 0; p < 2; p++) {
        int d  = d0 + p * 2;
        int kt = d >> 4, kd = d & 15;
        int lane = lane_lo + ((kd >> 1) & 3);
        size_t idx = (((size_t)mt * 16 + kt) * 32 + lane) * 4 + ((kd >> 3) * 2 + rh);
        split_store(qh, ql, idx, qa[p * 2], qa[p * 2 + 1]);
        split_store(wh, wl, idx, wa[p * 2], wa[p * 2 + 1]);
    }
}

// ---------------------------------------------------------------------------
// attn: fused dual-GEMM flash attention via mma.sync bf16 (3-term split).
// cp.async double-buffered, now 2 kt per stage (128KB dyn smem) -> half the
// barriers of round 5.
// ---------------------------------------------------------------------------
__global__ __launch_bounds__(512, 1) void attn_kernel(
    const float* __restrict__ bias,
    const int*   __restrict__ mask,
    float*       __restrict__ out)
{
    extern __shared__ __align__(16) char dsm[];
    __shared__ int   smask[NT];
    __shared__ float sM[2][128], sD[2][128], sN[2][128];

    const int tid  = threadIdx.x;
    const int lane = tid & 31;
    const int w    = tid >> 5;
    const int wm   = w >> 1;
    const int wt   = w & 1;
    const int l0   = blockIdx.x * 128;
    const int b    = blockIdx.y;
    const u32 smb  = smem_u32(dsm);

    smask[tid] = mask[b * NT + tid];

    const int grp = tid >> 7;
    const int gi  = tid & 127;
    const uint4* Asrc = (grp == 0) ? g_Qh : (grp == 1) ? g_Ql : (grp == 2) ? g_Wh : g_Wl;
    const uint4* Bsrc = (grp == 0) ? g_Kh : (grp == 1) ? g_Kl : (grp == 2) ? g_Vh : g_Vl;
    const int amt0 = gi >> 5,          aln0 = gi & 31;
    const int amt1 = (gi + 128) >> 5,  aln1 = gi & 31;
    const int bnt0 = gi >> 4,          blp0 = gi & 15;
    const int bnt1 = (gi + 128) >> 4,  blp1 = gi & 15;

    const size_t aRow = (size_t)blockIdx.x * 8;

    float mrun[2] = {-1e30f, -1e30f}, dnr[2] = {0.f, 0.f}, nmr[2] = {0.f, 0.f};

    for (int chunk = 0; chunk < 4; chunk++) {
        float sacc[32], uacc[32];
#pragma unroll
        for (int x = 0; x < 32; x++) { sacc[x] = 0.f; uacc[x] = 0.f; }

        const size_t bRow = (size_t)b * 64 + chunk * 16;

        auto loadStage = [&](int buf, int kt0) {
#pragma unroll
            for (int s = 0; s < 2; s++) {
                int kt = kt0 + s;
                u32 base = smb + buf * 65536 + s * 32768 + grp * 4096;
                cpasync16(base + (amt0 * 32 + aln0) * 16,
                          Asrc + ((aRow + amt0) * 16 + kt) * 32 + aln0);
                cpasync16(base + (amt1 * 32 + aln1) * 16,
                          Asrc + ((aRow + amt1) * 16 + kt) * 32 + aln1);
                u32 bbase = base + 16384;
                cpasync16(bbase + (bnt0 * 16 + blp0) * 16,
                          Bsrc + ((bRow + bnt0) * 16 + kt) * 16 + blp0);
                cpasync16(bbase + (bnt1 * 16 + blp1) * 16,
                          Bsrc + ((bRow + bnt1) * 16 + kt) * 16 + blp1);
            }
            CP_COMMIT();
        };

        loadStage(0, 0);
        CP_WAIT0();
        __syncthreads();

        for (int ks = 0; ks < 8; ks++) {
            const int buf = ks & 1;
            if (ks < 7) loadStage(buf ^ 1, (ks + 1) * 2);
#pragma unroll
            for (int s = 0; s < 2; s++) {
                const char* sb = dsm + buf * 65536 + s * 32768;
                uint4 qh = *(const uint4*)(sb +          (wm * 32 + lane) * 16);
                uint4 ql = *(const uint4*)(sb + 4096  +  (wm * 32 + lane) * 16);
                uint4 wh = *(const uint4*)(sb + 8192  +  (wm * 32 + lane) * 16);
                uint4 wl = *(const uint4*)(sb + 12288 +  (wm * 32 + lane) * 16);
                const char* bb = sb + 16384;
#pragma unroll
                for (int j = 0; j < 8; j++) {
                    int nt = wt * 8 + j;
                    uint2 kh = *(const uint2*)(bb +          (nt * 32 + lane) * 8);
                    uint2 kl = *(const uint2*)(bb + 4096  +  (nt * 32 + lane) * 8);
                    uint2 vh = *(const uint2*)(bb + 8192  +  (nt * 32 + lane) * 8);
                    uint2 vl = *(const uint2*)(bb + 12288 +  (nt * 32 + lane) * 8);
                    mma16816(&sacc[j * 4], qh, kh);
                    mma16816(&sacc[j * 4], qh, kl);
                    mma16816(&sacc[j * 4], ql, kh);
                    mma16816(&uacc[j * 4], wh, vh);
                    mma16816(&uacc[j * 4], wh, vl);
                    mma16816(&uacc[j * 4], wl, vh);
                }
            }
            if (ks < 7) CP_WAIT0();
            __syncthreads();
        }

        const int cbase = chunk * 128 + wt * 64 + (lane & 3) * 2;
#pragma unroll
        for (int h = 0; h < 2; h++) {
            float mloc = -1e30f;
            int   mk[16];
            float sv[16];
#pragma unroll
            for (int j = 0; j < 8; j++)
#pragma unroll
                for (int e = 0; e < 2; e++) {
                    int idx = j * 2 + e;
                    mk[idx] = smask[cbase + j * 8 + e];
                    sv[idx] = sacc[j * 4 + h * 2 + e];
                    if (mk[idx]) mloc = fmaxf(mloc, sv[idx]);
                }
            mloc = fmaxf(mloc, __shfl_xor_sync(0xFFFFFFFFu, mloc, 1));
            mloc = fmaxf(mloc, __shfl_xor_sync(0xFFFFFFFFu, mloc, 2));
            float newm = fmaxf(mrun[h], mloc);
            float f = __expf(mrun[h] - newm);
            float ds = 0.f, ns = 0.f;
#pragma unroll
            for (int j = 0; j < 8; j++)
#pragma unroll
                for (int e = 0; e < 2; e++) {
                    int idx = j * 2 + e;
                    float p = mk[idx] ? __expf(sv[idx] - newm) : 0.f;
                    ds += p;
                    ns += p * uacc[j * 4 + h * 2 + e];
                }
            ds += __shfl_xor_sync(0xFFFFFFFFu, ds, 1);
            ds += __shfl_xor_sync(0xFFFFFFFFu, ds, 2);
            ns += __shfl_xor_sync(0xFFFFFFFFu, ns, 1);
            ns += __shfl_xor_sync(0xFFFFFFFFu, ns, 2);
            dnr[h] = dnr[h] * f + ds;
            nmr[h] = nmr[h] * f + ns;
            mrun[h] = newm;
        }
    }

    if ((lane & 3) == 0) {
#pragma unroll
        for (int h = 0; h < 2; h++) {
            int rl = wm * 16 + (lane >> 2) + h * 8;
            sM[wt][rl] = mrun[h];
            sD[wt][rl] = dnr[h];
            sN[wt][rl] = nmr[h];
        }
    }
    __syncthreads();
    if (tid < 128) {
        float m0 = sM[0][tid], m1 = sM[1][tid];
        float mm = fmaxf(m0, m1);
        float f0 = __expf(m0 - mm), f1 = __expf(m1 - mm);
        float dn = sD[0][tid] * f0 + sD[1][tid] * f1;
        float nm = sN[0][tid] * f0 + sN[1][tid] * f1;
        out[b * NL + l0 + tid] = nm / dn + bias[l0 + tid];
    }
}

extern "C" void kernel_launch(void* const* d_in, const int* in_sizes, int n_in,
                              void* d_out, int out_size) {
    const float* X       = (const float*)d_in[0];
    const int*   mask    = (const int*)  d_in[1];
    const float* queries = (const float*)d_in[2];
    const float* Wk      = (const float*)d_in[3];
    const float* Wv      = (const float*)d_in[4];
    const float* outw    = (const float*)d_in[5];
    const float* bias    = (const float*)d_in[6];
    float* out = (float*)d_out;

    split_x<<<(NB * NT * NH / 4 + 255) / 256, 256>>>(X);
    dim3 gw((ND * NH / 4 + 255) / 256, 2);
    split_w<<<gw, 256>>>(Wk, Wv);
    split_qw<<<(NL * ND / 4 + 255) / 256, 256>>>(queries, outw);

    cudaFuncSetAttribute(kv_mma, cudaFuncAttributeMaxDynamicSharedMemorySize, 65536);
    dim3 g1(64, 4);
    kv_mma<<<g1, 512, 65536>>>(0);

    cudaFuncSetAttribute(attn_kernel, cudaFuncAttributeMaxDynamicSharedMemorySize, 131072);
    dim3 g2(64, 16);
    attn_kernel<<<g2, 512, 131072>>>(bias, mask, out);
}